// round 1
// baseline (speedup 1.0000x reference)
#include <cuda_runtime.h>
#include <math.h>

#define C_ 128
#define H_ 32
#define K_ 15
#define G_ 8
#define HID_ 32
#define KG_ 120
#define W1P 132   // padded pitch for W1^T rows [32][132]
#define W2P 36    // padded pitch for W2^T rows [128][36]
#define WARPS 8
#define THREADS 256
#define NBLK 592

// Per-warp smem region: csm[128] + hsm[32] + cwsm[128] + ws[256] + idx[32] = 576+16... = 592 floats
#define WARP_SMEM 592
// block-wide: W1t(32*132) + W2t(128*36) + b1(32) + b2(128) + kp(48) + psum(128) + psq(128)
#define BLOCK_FIXED (32*W1P + 128*W2P + 32 + 128 + 48 + 128 + 128)
#define SMEM_FLOATS (BLOCK_FIXED + WARPS*WARP_SMEM)

__device__ float g_sum[C_];
__device__ float g_sq[C_];
__device__ float g_scale[C_];
__device__ float g_shift[C_];

__global__ void kp_zero_kernel() {
    int t = threadIdx.x;
    if (t < C_) { g_sum[t] = 0.f; g_sq[t] = 0.f; }
}

__global__ __launch_bounds__(THREADS) void kp_main_kernel(
    const float* __restrict__ qp,   // (M,3)
    const float* __restrict__ sp,   // (N,3)
    const float* __restrict__ sf,   // (N,128)
    const int*   __restrict__ nidx, // (M,32)
    const float* __restrict__ kp,   // (15,3)
    const float* __restrict__ W1,   // (128,32)
    const float* __restrict__ b1,   // (32)
    const float* __restrict__ W2,   // (32,120)
    const float* __restrict__ b2,   // (120)
    float* __restrict__ out,        // (M,128) pre-BN
    int M)
{
    extern __shared__ float smem[];
    float* W1t  = smem;                 // [32][132]  W1t[i*W1P+c] = W1[c][i]
    float* W2t  = W1t + 32 * W1P;       // [128][36]  W2t[kg*W2P+i] = W2[i][kg]
    float* b1s  = W2t + 128 * W2P;      // [32]
    float* b2s  = b1s + 32;             // [128] (padded, 120 real)
    float* kps  = b2s + 128;            // [48]  (45 real)
    float* psum = kps + 48;             // [128]
    float* psq  = psum + 128;           // [128]
    float* wreg = psq + 128;            // per-warp regions

    const int tid  = threadIdx.x;
    const int wid  = tid >> 5;
    const int lane = tid & 31;

    float* csm  = wreg + wid * WARP_SMEM; // [128] center feats
    float* hsm  = csm + 128;              // [32]  hidden vec
    float* cwsm = hsm + 32;               // [128] conv weights (120 real, padded 0)
    float* ws   = cwsm + 128;             // [256] combined W[h][g]
    int*   idxs = (int*)(ws + 256);       // [32]

    // cooperative loads (one-time per block)
    for (int e = tid; e < 128 * 32; e += THREADS) {
        int c = e >> 5, i = e & 31;
        W1t[i * W1P + c] = W1[e];           // W1 is [c][i], e = c*32+i
    }
    for (int e = tid; e < 128 * 32; e += THREADS) {
        int i = e >> 7, kg = e & 127;
        W2t[kg * W2P + i] = (kg < KG_) ? W2[i * KG_ + kg] : 0.f;
    }
    if (tid < 32)  b1s[tid] = b1[tid];
    if (tid < 128) { b2s[tid] = (tid < KG_) ? b2[tid] : 0.f; psum[tid] = 0.f; psq[tid] = 0.f; }
    if (tid < 45)  kps[tid] = kp[tid];
    __syncthreads();

    float lsum0 = 0.f, lsum1 = 0.f, lsum2 = 0.f, lsum3 = 0.f;
    float lsq0 = 0.f, lsq1 = 0.f, lsq2 = 0.f, lsq3 = 0.f;

    const int gw = blockIdx.x * WARPS + wid;
    const int nw = gridDim.x * WARPS;
    const int g  = lane >> 2;   // group owned by this lane (channels 4*lane..+3 are in group lane/4)

    for (int m = gw; m < M; m += nw) {
        // ---- neighbor index + influence (lane plays role of h) ----
        int myidx = nidx[m * H_ + lane];
        idxs[lane] = myidx;
        float qx = qp[m * 3 + 0], qy = qp[m * 3 + 1], qz = qp[m * 3 + 2];
        float dx = sp[myidx * 3 + 0] - qx;
        float dy = sp[myidx * 3 + 1] - qy;
        float dz = sp[myidx * 3 + 2] - qz;
        float infl[K_];
        #pragma unroll
        for (int k = 0; k < K_; k++) {
            float tx = dx - kps[k * 3 + 0];
            float ty = dy - kps[k * 3 + 1];
            float tz = dz - kps[k * 3 + 2];
            float sq = fmaf(tx, tx, fmaf(ty, ty, tz * tz));
            float d  = sqrtf(sq);
            infl[k]  = fmaxf(1.f - 0.5f * d, 0.f);   // SIGMA = 2
        }
        __syncwarp();

        // ---- center feats into smem ----
        int idx0 = idxs[0];
        float4 cf = __ldg(&((const float4*)sf)[idx0 * 32 + lane]);
        ((float4*)csm)[lane] = cf;
        __syncwarp();

        // ---- hvec[lane] = leaky(b1 + center . W1[:,lane]) ----
        float hv = b1s[lane];
        #pragma unroll 8
        for (int cc = 0; cc < 32; cc++) {
            float4 c4 = ((float4*)csm)[cc];
            float4 w4 = *(float4*)&W1t[lane * W1P + cc * 4];
            hv = fmaf(c4.x, w4.x, hv);
            hv = fmaf(c4.y, w4.y, hv);
            hv = fmaf(c4.z, w4.z, hv);
            hv = fmaf(c4.w, w4.w, hv);
        }
        hv = (hv > 0.f) ? hv : 0.1f * hv;
        hsm[lane] = hv;
        __syncwarp();

        // ---- conv_w[kg] = b2 + hvec . W2[:,kg]  (lane handles 4 kg values) ----
        #pragma unroll
        for (int r = 0; r < 4; r++) {
            int kg = lane + 32 * r;
            float acc = b2s[kg];
            #pragma unroll
            for (int ii = 0; ii < 8; ii++) {
                float4 h4 = ((float4*)hsm)[ii];
                float4 w4 = *(float4*)&W2t[kg * W2P + ii * 4];
                acc = fmaf(h4.x, w4.x, acc);
                acc = fmaf(h4.y, w4.y, acc);
                acc = fmaf(h4.z, w4.z, acc);
                acc = fmaf(h4.w, w4.w, acc);
            }
            cwsm[kg] = acc;   // pad rows (kg>=120) end up 0 (W2t pad = 0, b2s pad = 0)
        }
        __syncwarp();

        // ---- combine: W[h][g] = sum_k infl[k] * conv_w[k][g]  (lane plays role of h) ----
        {
            float w0 = 0, w1 = 0, w2 = 0, w3 = 0, w4v = 0, w5 = 0, w6 = 0, w7 = 0;
            #pragma unroll
            for (int k = 0; k < K_; k++) {
                float4 a = ((float4*)cwsm)[k * 2];
                float4 b = ((float4*)cwsm)[k * 2 + 1];
                float ik = infl[k];
                w0 = fmaf(ik, a.x, w0); w1 = fmaf(ik, a.y, w1);
                w2 = fmaf(ik, a.z, w2); w3 = fmaf(ik, a.w, w3);
                w4v = fmaf(ik, b.x, w4v); w5 = fmaf(ik, b.y, w5);
                w6 = fmaf(ik, b.z, w6); w7 = fmaf(ik, b.w, w7);
            }
            ((float4*)ws)[lane * 2 + 0] = make_float4(w0, w1, w2, w3);
            ((float4*)ws)[lane * 2 + 1] = make_float4(w4v, w5, w6, w7);
        }
        __syncwarp();

        // ---- main gather-accumulate: out[c] = sum_h W[h][g(c)] * feats[idx[h]][c] ----
        float a0 = 0.f, a1 = 0.f, a2 = 0.f, a3 = 0.f;
        #pragma unroll 4
        for (int h = 0; h < H_; h++) {
            float wv = ws[h * 8 + g];
            int ih = idxs[h];
            float4 f = __ldg(&((const float4*)sf)[ih * 32 + lane]);
            a0 = fmaf(wv, f.x, a0);
            a1 = fmaf(wv, f.y, a1);
            a2 = fmaf(wv, f.z, a2);
            a3 = fmaf(wv, f.w, a3);
        }
        ((float4*)out)[m * 32 + lane] = make_float4(a0, a1, a2, a3);
        lsum0 += a0; lsum1 += a1; lsum2 += a2; lsum3 += a3;
        lsq0 = fmaf(a0, a0, lsq0); lsq1 = fmaf(a1, a1, lsq1);
        lsq2 = fmaf(a2, a2, lsq2); lsq3 = fmaf(a3, a3, lsq3);
        __syncwarp();   // protect idxs/csm/ws reuse next iteration
    }

    // ---- block reduction of BN statistics, then global atomics ----
    __syncthreads();
    int cb = lane * 4;
    atomicAdd(&psum[cb + 0], lsum0); atomicAdd(&psq[cb + 0], lsq0);
    atomicAdd(&psum[cb + 1], lsum1); atomicAdd(&psq[cb + 1], lsq1);
    atomicAdd(&psum[cb + 2], lsum2); atomicAdd(&psq[cb + 2], lsq2);
    atomicAdd(&psum[cb + 3], lsum3); atomicAdd(&psq[cb + 3], lsq3);
    __syncthreads();
    if (tid < 128) {
        atomicAdd(&g_sum[tid], psum[tid]);
        atomicAdd(&g_sq[tid],  psq[tid]);
    }
}

__global__ void kp_stats_kernel(const float* __restrict__ gamma,
                                const float* __restrict__ beta, float invM) {
    int c = threadIdx.x;
    if (c < C_) {
        float mean = g_sum[c] * invM;
        float var  = fmaxf(g_sq[c] * invM - mean * mean, 0.f);
        float inv  = rsqrtf(var + 1e-5f);
        float sc   = gamma[c] * inv;
        g_scale[c] = sc;
        g_shift[c] = beta[c] - mean * sc;
    }
}

__global__ void kp_norm_kernel(float* __restrict__ out, int total4) {
    int i = blockIdx.x * blockDim.x + threadIdx.x;
    if (i < total4) {
        float4 v = ((float4*)out)[i];
        int cb = (i & 31) * 4;
        float s0 = g_scale[cb + 0], s1 = g_scale[cb + 1], s2 = g_scale[cb + 2], s3 = g_scale[cb + 3];
        float t0 = g_shift[cb + 0], t1 = g_shift[cb + 1], t2 = g_shift[cb + 2], t3 = g_shift[cb + 3];
        v.x = fmaf(v.x, s0, t0); v.y = fmaf(v.y, s1, t1);
        v.z = fmaf(v.z, s2, t2); v.w = fmaf(v.w, s3, t3);
        v.x = (v.x > 0.f) ? v.x : 0.1f * v.x;
        v.y = (v.y > 0.f) ? v.y : 0.1f * v.y;
        v.z = (v.z > 0.f) ? v.z : 0.1f * v.z;
        v.w = (v.w > 0.f) ? v.w : 0.1f * v.w;
        ((float4*)out)[i] = v;
    }
}

extern "C" void kernel_launch(void* const* d_in, const int* in_sizes, int n_in,
                              void* d_out, int out_size) {
    const float* qp    = (const float*)d_in[0];
    const float* sp    = (const float*)d_in[1];
    const float* sf    = (const float*)d_in[2];
    const int*   nidx  = (const int*)d_in[3];
    const float* kp    = (const float*)d_in[4];
    const float* W1    = (const float*)d_in[5];
    const float* b1    = (const float*)d_in[6];
    const float* W2    = (const float*)d_in[7];
    const float* b2    = (const float*)d_in[8];
    const float* gamma = (const float*)d_in[9];
    const float* beta  = (const float*)d_in[10];
    float* out = (float*)d_out;

    int M = in_sizes[0] / 3;

    size_t smem_bytes = (size_t)SMEM_FLOATS * sizeof(float);
    cudaFuncSetAttribute(kp_main_kernel,
                         cudaFuncAttributeMaxDynamicSharedMemorySize, (int)smem_bytes);

    kp_zero_kernel<<<1, 128>>>();
    kp_main_kernel<<<NBLK, THREADS, smem_bytes>>>(qp, sp, sf, nidx, kp, W1, b1, W2, b2, out, M);
    kp_stats_kernel<<<1, 128>>>(gamma, beta, 1.0f / (float)M);
    int total4 = M * 32;
    kp_norm_kernel<<<(total4 + 255) / 256, 256>>>(out, total4);
}

// round 3
// speedup vs baseline: 1.0464x; 1.0464x over previous
#include <cuda_runtime.h>
#include <cuda_fp16.h>
#include <math.h>

#define C_ 128
#define H_ 32
#define K_ 15
#define KG_ 120
#define W1P 132   // padded pitch for W1^T rows [32][132]
#define W2P 36    // padded pitch for W2^T rows [128][36]
#define WARPS 8
#define THREADS 256
#define NBLK 592
#define NMAX 30720

// Per-warp smem region: csm[128] + hsm[32] + cwsm[128] + ws[256] + idx[32] = 576 floats + pad
#define WARP_SMEM 592
#define BLOCK_FIXED (32*W1P + 128*W2P + 32 + 128 + 48 + 128 + 128)
#define SMEM_FLOATS (BLOCK_FIXED + WARPS*WARP_SMEM)

__device__ float g_sum[C_];
__device__ float g_sq[C_];
__device__ __align__(16) __half g_sf16[NMAX * C_];

__global__ void kp_zero_kernel() {
    int t = threadIdx.x;
    if (t < C_) { g_sum[t] = 0.f; g_sq[t] = 0.f; }
}

// convert s_feats fp32 -> fp16 cache (one float4 -> 2x half2 per thread)
__global__ void kp_cvt_kernel(const float* __restrict__ sf, int total4) {
    int i = blockIdx.x * blockDim.x + threadIdx.x;
    if (i < total4) {
        float4 v = ((const float4*)sf)[i];
        __half2 h0 = __floats2half2_rn(v.x, v.y);
        __half2 h1 = __floats2half2_rn(v.z, v.w);
        uint2 p;
        p.x = *(unsigned int*)&h0;
        p.y = *(unsigned int*)&h1;
        ((uint2*)g_sf16)[i] = p;
    }
}

__global__ __launch_bounds__(THREADS) void kp_main_kernel(
    const float* __restrict__ qp,   // (M,3)
    const float* __restrict__ sp,   // (N,3)
    const float* __restrict__ sf,   // (N,128) fp32 (center feats only)
    const int*   __restrict__ nidx, // (M,32)
    const float* __restrict__ kp,   // (15,3)
    const float* __restrict__ W1,   // (128,32)
    const float* __restrict__ b1,   // (32)
    const float* __restrict__ W2,   // (32,120)
    const float* __restrict__ b2,   // (120)
    float* __restrict__ out,        // (M,128) pre-BN
    int M)
{
    extern __shared__ float smem[];
    float* W1t  = smem;                 // [32][132]
    float* W2t  = W1t + 32 * W1P;       // [128][36]
    float* b1s  = W2t + 128 * W2P;      // [32]
    float* b2s  = b1s + 32;             // [128]
    float* kps  = b2s + 128;            // [48]
    float* psum = kps + 48;             // [128]
    float* psq  = psum + 128;           // [128]
    float* wreg = psq + 128;

    const int tid  = threadIdx.x;
    const int wid  = tid >> 5;
    const int lane = tid & 31;

    float* csm  = wreg + wid * WARP_SMEM; // [128]
    float* hsm  = csm + 128;              // [32]
    float* cwsm = hsm + 32;               // [128]
    float* ws   = cwsm + 128;             // [256]
    int*   idxs = (int*)(ws + 256);       // [32]

    for (int e = tid; e < 128 * 32; e += THREADS) {
        int c = e >> 5, i = e & 31;
        W1t[i * W1P + c] = W1[e];
    }
    for (int e = tid; e < 128 * 32; e += THREADS) {
        int i = e >> 7, kg = e & 127;
        W2t[kg * W2P + i] = (kg < KG_) ? W2[i * KG_ + kg] : 0.f;
    }
    if (tid < 32)  b1s[tid] = b1[tid];
    if (tid < 128) { b2s[tid] = (tid < KG_) ? b2[tid] : 0.f; psum[tid] = 0.f; psq[tid] = 0.f; }
    if (tid < 45)  kps[tid] = kp[tid];
    __syncthreads();

    float lsum0 = 0.f, lsum1 = 0.f, lsum2 = 0.f, lsum3 = 0.f;
    float lsq0 = 0.f, lsq1 = 0.f, lsq2 = 0.f, lsq3 = 0.f;

    const int gw = blockIdx.x * WARPS + wid;
    const int nw = gridDim.x * WARPS;
    const int g  = lane >> 2;

    for (int m = gw; m < M; m += nw) {
        // ---- influence (lane = h) ----
        int myidx = nidx[m * H_ + lane];
        idxs[lane] = myidx;
        float qx = qp[m * 3 + 0], qy = qp[m * 3 + 1], qz = qp[m * 3 + 2];
        float dx = sp[myidx * 3 + 0] - qx;
        float dy = sp[myidx * 3 + 1] - qy;
        float dz = sp[myidx * 3 + 2] - qz;
        float infl[K_];
        #pragma unroll
        for (int k = 0; k < K_; k++) {
            float tx = dx - kps[k * 3 + 0];
            float ty = dy - kps[k * 3 + 1];
            float tz = dz - kps[k * 3 + 2];
            float sq = fmaf(tx, tx, fmaf(ty, ty, tz * tz));
            infl[k]  = fmaxf(1.f - 0.5f * sqrtf(sq), 0.f);
        }
        __syncwarp();

        // ---- center feats (fp32) ----
        int idx0 = idxs[0];
        float4 cf = __ldg(&((const float4*)sf)[idx0 * 32 + lane]);
        ((float4*)csm)[lane] = cf;
        __syncwarp();

        // ---- hvec[lane] = leaky(b1 + center . W1[:,lane]) ----
        float hv = b1s[lane];
        #pragma unroll 8
        for (int cc = 0; cc < 32; cc++) {
            float4 c4 = ((float4*)csm)[cc];
            float4 w4 = *(float4*)&W1t[lane * W1P + cc * 4];
            hv = fmaf(c4.x, w4.x, hv);
            hv = fmaf(c4.y, w4.y, hv);
            hv = fmaf(c4.z, w4.z, hv);
            hv = fmaf(c4.w, w4.w, hv);
        }
        hv = (hv > 0.f) ? hv : 0.1f * hv;
        hsm[lane] = hv;
        __syncwarp();

        // ---- conv_w (lane covers 4 kg) ----
        #pragma unroll
        for (int r = 0; r < 4; r++) {
            int kg = lane + 32 * r;
            float acc = b2s[kg];
            #pragma unroll
            for (int ii = 0; ii < 8; ii++) {
                float4 h4 = ((float4*)hsm)[ii];
                float4 w4 = *(float4*)&W2t[kg * W2P + ii * 4];
                acc = fmaf(h4.x, w4.x, acc);
                acc = fmaf(h4.y, w4.y, acc);
                acc = fmaf(h4.z, w4.z, acc);
                acc = fmaf(h4.w, w4.w, acc);
            }
            cwsm[kg] = acc;
        }
        __syncwarp();

        // ---- W[h][g] = sum_k infl[k]*conv_w[k][g] (lane = h) ----
        {
            float w0 = 0, w1 = 0, w2 = 0, w3 = 0, w4v = 0, w5 = 0, w6 = 0, w7 = 0;
            #pragma unroll
            for (int k = 0; k < K_; k++) {
                float4 a = ((float4*)cwsm)[k * 2];
                float4 b = ((float4*)cwsm)[k * 2 + 1];
                float ik = infl[k];
                w0 = fmaf(ik, a.x, w0); w1 = fmaf(ik, a.y, w1);
                w2 = fmaf(ik, a.z, w2); w3 = fmaf(ik, a.w, w3);
                w4v = fmaf(ik, b.x, w4v); w5 = fmaf(ik, b.y, w5);
                w6 = fmaf(ik, b.z, w6); w7 = fmaf(ik, b.w, w7);
            }
            ((float4*)ws)[lane * 2 + 0] = make_float4(w0, w1, w2, w3);
            ((float4*)ws)[lane * 2 + 1] = make_float4(w4v, w5, w6, w7);
        }
        __syncwarp();

        // ---- gather-accumulate over fp16 feature cache ----
        float a0 = 0.f, a1 = 0.f, a2 = 0.f, a3 = 0.f;
        #pragma unroll 8
        for (int h = 0; h < H_; h++) {
            float wv = ws[h * 8 + g];
            int ih = idxs[h];
            uint2 f = *(const uint2*)(g_sf16 + ih * C_ + lane * 4);
            __half2 h0 = *(__half2*)&f.x;
            __half2 h1 = *(__half2*)&f.y;
            float2 f0 = __half22float2(h0);
            float2 f1 = __half22float2(h1);
            a0 = fmaf(wv, f0.x, a0);
            a1 = fmaf(wv, f0.y, a1);
            a2 = fmaf(wv, f1.x, a2);
            a3 = fmaf(wv, f1.y, a3);
        }
        ((float4*)out)[m * 32 + lane] = make_float4(a0, a1, a2, a3);
        lsum0 += a0; lsum1 += a1; lsum2 += a2; lsum3 += a3;
        lsq0 = fmaf(a0, a0, lsq0); lsq1 = fmaf(a1, a1, lsq1);
        lsq2 = fmaf(a2, a2, lsq2); lsq3 = fmaf(a3, a3, lsq3);
        __syncwarp();
    }

    __syncthreads();
    int cb = lane * 4;
    atomicAdd(&psum[cb + 0], lsum0); atomicAdd(&psq[cb + 0], lsq0);
    atomicAdd(&psum[cb + 1], lsum1); atomicAdd(&psq[cb + 1], lsq1);
    atomicAdd(&psum[cb + 2], lsum2); atomicAdd(&psq[cb + 2], lsq2);
    atomicAdd(&psum[cb + 3], lsum3); atomicAdd(&psq[cb + 3], lsq3);
    __syncthreads();
    if (tid < 128) {
        atomicAdd(&g_sum[tid], psum[tid]);
        atomicAdd(&g_sq[tid],  psq[tid]);
    }
}

// fused stats + normalize + leaky
__global__ __launch_bounds__(256) void kp_norm_kernel(
    float* __restrict__ out,
    const float* __restrict__ gamma,
    const float* __restrict__ beta,
    float invM, int total4)
{
    __shared__ float ssc[128], ssh[128];
    int t = threadIdx.x;
    if (t < 128) {
        float mean = g_sum[t] * invM;
        float var  = fmaxf(g_sq[t] * invM - mean * mean, 0.f);
        float sc   = gamma[t] * rsqrtf(var + 1e-5f);
        ssc[t] = sc;
        ssh[t] = beta[t] - mean * sc;
    }
    __syncthreads();

    int i = blockIdx.x * blockDim.x + t;
    if (i < total4) {
        float4 v = ((float4*)out)[i];
        int cb = (i & 31) * 4;
        v.x = fmaf(v.x, ssc[cb + 0], ssh[cb + 0]);
        v.y = fmaf(v.y, ssc[cb + 1], ssh[cb + 1]);
        v.z = fmaf(v.z, ssc[cb + 2], ssh[cb + 2]);
        v.w = fmaf(v.w, ssc[cb + 3], ssh[cb + 3]);
        v.x = (v.x > 0.f) ? v.x : 0.1f * v.x;
        v.y = (v.y > 0.f) ? v.y : 0.1f * v.y;
        v.z = (v.z > 0.f) ? v.z : 0.1f * v.z;
        v.w = (v.w > 0.f) ? v.w : 0.1f * v.w;
        ((float4*)out)[i] = v;
    }
}

extern "C" void kernel_launch(void* const* d_in, const int* in_sizes, int n_in,
                              void* d_out, int out_size) {
    const float* qp    = (const float*)d_in[0];
    const float* sp    = (const float*)d_in[1];
    const float* sf    = (const float*)d_in[2];
    const int*   nidx  = (const int*)d_in[3];
    const float* kp    = (const float*)d_in[4];
    const float* W1    = (const float*)d_in[5];
    const float* b1    = (const float*)d_in[6];
    const float* W2    = (const float*)d_in[7];
    const float* b2    = (const float*)d_in[8];
    const float* gamma = (const float*)d_in[9];
    const float* beta  = (const float*)d_in[10];
    float* out = (float*)d_out;

    int M = in_sizes[0] / 3;
    int N = in_sizes[2] / C_;
    if (N > NMAX) N = NMAX;   // safety clamp (N is 30000 in this problem)

    size_t smem_bytes = (size_t)SMEM_FLOATS * sizeof(float);
    cudaFuncSetAttribute(kp_main_kernel,
                         cudaFuncAttributeMaxDynamicSharedMemorySize, (int)smem_bytes);

    kp_zero_kernel<<<1, 128>>>();
    int cvt4 = N * 32;
    kp_cvt_kernel<<<(cvt4 + 255) / 256, 256>>>(sf, cvt4);
    kp_main_kernel<<<NBLK, THREADS, smem_bytes>>>(qp, sp, sf, nidx, kp, W1, b1, W2, b2, out, M);
    int total4 = M * 32;
    kp_norm_kernel<<<(total4 + 255) / 256, 256>>>(out, gamma, beta, 1.0f / (float)M, total4);
}

// round 4
// speedup vs baseline: 1.6198x; 1.5480x over previous
#include <cuda_runtime.h>
#include <cuda_fp16.h>
#include <math.h>

#define C_ 128
#define H_ 32
#define K_ 15
#define KG_ 120
#define QB 4
#define W1P 132   // pitch W1^T [32][132]; lane*132 mod 32 = 4*lane -> conflict-free per quarter-warp
#define W2P 36    // pitch W2^T [128][36]; same property
#define WARPS 8
#define THREADS 256
#define NBLK 296
#define NMAX 30720

// per-warp region (floats): csm 4*128 | hsm 4*32 | cwsm 4*128 | ws 256 | idxs 4*32 | pad
#define OFF_CSM  0
#define OFF_HSM  512
#define OFF_CWSM 640
#define OFF_WS   1152
#define OFF_IDX  1408
#define WARP_SMEM 1544
#define BLOCK_FIXED (32*W1P + 128*W2P + 32 + 128 + 48 + 128 + 128)   // 9296
#define SMEM_FLOATS (BLOCK_FIXED + WARPS*WARP_SMEM)                   // 21648 fl = 86.6KB

typedef unsigned long long ull;
#define FMA2(d,a,b,c) asm("fma.rn.f32x2 %0, %1, %2, %3;" : "=l"(d) : "l"(a), "l"(b), "l"(c))
#define ADD2(d,a,b)   asm("add.rn.f32x2 %0, %1, %2;" : "=l"(d) : "l"(a), "l"(b))
#define PACK2(d,x)    asm("mov.b64 %0, {%1, %1};" : "=l"(d) : "f"(x))
#define UNPK2(lo,hi,p) asm("mov.b64 {%0, %1}, %2;" : "=f"(lo), "=f"(hi) : "l"(p))

__device__ float g_sum[C_];
__device__ float g_sq[C_];
__device__ __align__(16) __half g_sf16[NMAX * C_];

__global__ void kp_zero_kernel() {
    int t = threadIdx.x;
    if (t < C_) { g_sum[t] = 0.f; g_sq[t] = 0.f; }
}

__global__ void kp_cvt_kernel(const float* __restrict__ sf, int total4) {
    int i = blockIdx.x * blockDim.x + threadIdx.x;
    if (i < total4) {
        float4 v = ((const float4*)sf)[i];
        __half2 h0 = __floats2half2_rn(v.x, v.y);
        __half2 h1 = __floats2half2_rn(v.z, v.w);
        uint2 p;
        p.x = *(unsigned int*)&h0;
        p.y = *(unsigned int*)&h1;
        ((uint2*)g_sf16)[i] = p;
    }
}

__global__ __launch_bounds__(THREADS, 2) void kp_main_kernel(
    const float* __restrict__ qp,   // (M,3)
    const float* __restrict__ sp,   // (N,3)
    const float* __restrict__ sf,   // (N,128) fp32
    const int*   __restrict__ nidx, // (M,32)
    const float* __restrict__ kp,   // (15,3)
    const float* __restrict__ W1,   // (128,32)
    const float* __restrict__ b1,   // (32)
    const float* __restrict__ W2,   // (32,120)
    const float* __restrict__ b2,   // (120)
    float* __restrict__ out,        // (M,128) pre-BN
    int M)
{
    extern __shared__ float smem[];
    float* W1t  = smem;                 // [32][132]
    float* W2t  = W1t + 32 * W1P;       // [128][36]
    float* b1s  = W2t + 128 * W2P;      // [32]
    float* b2s  = b1s + 32;             // [128]
    float* kps  = b2s + 128;            // [48]
    float* psum = kps + 48;             // [128]
    float* psq  = psum + 128;           // [128]
    float* wreg = psq + 128;

    const int tid  = threadIdx.x;
    const int wid  = tid >> 5;
    const int lane = tid & 31;

    float* wbase = wreg + wid * WARP_SMEM;
    float* csm   = wbase + OFF_CSM;     // [4][128]
    float* hsm   = wbase + OFF_HSM;     // [4][32]
    float* cwsm  = wbase + OFF_CWSM;    // [4][128]
    float* ws    = wbase + OFF_WS;      // [32][8]
    int*   idxs  = (int*)(wbase + OFF_IDX); // [4][32]

    for (int e = tid; e < 128 * 32; e += THREADS) {
        int c = e >> 5, i = e & 31;
        W1t[i * W1P + c] = W1[e];
    }
    for (int e = tid; e < 128 * 32; e += THREADS) {
        int i = e >> 7, kg = e & 127;
        W2t[kg * W2P + i] = (kg < KG_) ? W2[i * KG_ + kg] : 0.f;
    }
    if (tid < 32)  b1s[tid] = b1[tid];
    if (tid < 128) { b2s[tid] = (tid < KG_) ? b2[tid] : 0.f; psum[tid] = 0.f; psq[tid] = 0.f; }
    if (tid < 45)  kps[tid] = kp[tid];
    __syncthreads();

    ull lsum01 = 0, lsum23 = 0, lsq01 = 0, lsq23 = 0;

    const int gw = blockIdx.x * WARPS + wid;
    const int nw = gridDim.x * WARPS;
    const int g  = lane >> 2;

    for (int mb = gw * QB; mb < M; mb += nw * QB) {
        // ---- A: neighbor indices + center feats for up to 4 queries ----
        int idxq[QB];
        #pragma unroll
        for (int q = 0; q < QB; q++) {
            int mq = mb + q;
            idxq[q] = (mq < M) ? nidx[mq * H_ + lane] : 0;
            idxs[q * 32 + lane] = idxq[q];
        }
        #pragma unroll
        for (int q = 0; q < QB; q++) {
            int i0 = __shfl_sync(0xffffffffu, idxq[q], 0);
            float4 cf = __ldg(&((const float4*)sf)[i0 * 32 + lane]);
            ((float4*)&csm[q * 128])[lane] = cf;
        }
        __syncwarp();

        // ---- B: batched MLP1 — hv[q][lane] = leaky(b1 + center_q . W1[:,lane]) ----
        {
            ull hvp[QB];
            #pragma unroll
            for (int q = 0; q < QB; q++) hvp[q] = 0;
            #pragma unroll 8
            for (int cc = 0; cc < 32; cc++) {
                ulonglong2 w = *(ulonglong2*)&W1t[lane * W1P + cc * 4];
                #pragma unroll
                for (int q = 0; q < QB; q++) {
                    ulonglong2 c = *(ulonglong2*)&csm[q * 128 + cc * 4];
                    FMA2(hvp[q], c.x, w.x, hvp[q]);
                    FMA2(hvp[q], c.y, w.y, hvp[q]);
                }
            }
            float bb = b1s[lane];
            #pragma unroll
            for (int q = 0; q < QB; q++) {
                float lo, hi; UNPK2(lo, hi, hvp[q]);
                float hv = bb + lo + hi;
                hv = (hv > 0.f) ? hv : 0.1f * hv;
                hsm[q * 32 + lane] = hv;
            }
        }
        __syncwarp();

        // ---- C: batched MLP2 — conv_w[q][kg], kg = lane + 32r ----
        {
            ull accp[4][QB];
            #pragma unroll
            for (int r = 0; r < 4; r++)
                #pragma unroll
                for (int q = 0; q < QB; q++) accp[r][q] = 0;
            #pragma unroll
            for (int ii = 0; ii < 8; ii++) {
                ulonglong2 h2[QB];
                #pragma unroll
                for (int q = 0; q < QB; q++)
                    h2[q] = *(ulonglong2*)&hsm[q * 32 + ii * 4];
                #pragma unroll
                for (int r = 0; r < 4; r++) {
                    ulonglong2 w = *(ulonglong2*)&W2t[(lane + 32 * r) * W2P + ii * 4];
                    #pragma unroll
                    for (int q = 0; q < QB; q++) {
                        FMA2(accp[r][q], h2[q].x, w.x, accp[r][q]);
                        FMA2(accp[r][q], h2[q].y, w.y, accp[r][q]);
                    }
                }
            }
            #pragma unroll
            for (int r = 0; r < 4; r++) {
                int kg = lane + 32 * r;
                float bb = b2s[kg];
                #pragma unroll
                for (int q = 0; q < QB; q++) {
                    float lo, hi; UNPK2(lo, hi, accp[r][q]);
                    cwsm[q * 128 + kg] = bb + lo + hi;
                }
            }
        }
        __syncwarp();

        // ---- D: per query — influence, combine, gather, write ----
        #pragma unroll 1
        for (int q = 0; q < QB; q++) {
            int mq = mb + q;
            if (mq >= M) break;

            // influence (lane = h)
            float qx = qp[mq * 3 + 0], qy = qp[mq * 3 + 1], qz = qp[mq * 3 + 2];
            int myidx = idxq[q];
            float dx = sp[myidx * 3 + 0] - qx;
            float dy = sp[myidx * 3 + 1] - qy;
            float dz = sp[myidx * 3 + 2] - qz;
            float infl[K_];
            #pragma unroll
            for (int k = 0; k < K_; k++) {
                float tx = dx - kps[k * 3 + 0];
                float ty = dy - kps[k * 3 + 1];
                float tz = dz - kps[k * 3 + 2];
                float sq = fmaf(tx, tx, fmaf(ty, ty, tz * tz));
                infl[k]  = fmaxf(1.f - 0.5f * sqrtf(sq), 0.f);
            }

            // combine: W[h=lane][g] = sum_k infl[k] * conv_w[k][g]
            {
                ull w01 = 0, w23 = 0, w45 = 0, w67 = 0;
                const float* cwq = &cwsm[q * 128];
                #pragma unroll
                for (int k = 0; k < K_; k++) {
                    ulonglong2 p0 = *(ulonglong2*)&cwq[k * 8];
                    ulonglong2 p1 = *(ulonglong2*)&cwq[k * 8 + 4];
                    ull ik2; PACK2(ik2, infl[k]);
                    FMA2(w01, ik2, p0.x, w01);
                    FMA2(w23, ik2, p0.y, w23);
                    FMA2(w45, ik2, p1.x, w45);
                    FMA2(w67, ik2, p1.y, w67);
                }
                ulonglong2* wrow = (ulonglong2*)&ws[lane * 8];
                wrow[0] = make_ulonglong2(w01, w23);
                wrow[1] = make_ulonglong2(w45, w67);
            }
            __syncwarp();

            // gather-accumulate over fp16 cache
            ull a01 = 0, a23 = 0;
            const int* iq = &idxs[q * 32];
            #pragma unroll 16
            for (int h = 0; h < H_; h++) {
                float wv = ws[h * 8 + g];
                ull wv2; PACK2(wv2, wv);
                int ih = iq[h];
                uint2 f = *(const uint2*)(g_sf16 + ih * C_ + lane * 4);
                float2 lo = __half22float2(*(__half2*)&f.x);
                float2 hi = __half22float2(*(__half2*)&f.y);
                ull plo = *(ull*)&lo;
                ull phi = *(ull*)&hi;
                FMA2(a01, plo, wv2, a01);
                FMA2(a23, phi, wv2, a23);
            }
            float x0, x1, x2, x3;
            UNPK2(x0, x1, a01);
            UNPK2(x2, x3, a23);
            ((float4*)out)[mq * 32 + lane] = make_float4(x0, x1, x2, x3);
            ADD2(lsum01, lsum01, a01);
            ADD2(lsum23, lsum23, a23);
            FMA2(lsq01, a01, a01, lsq01);
            FMA2(lsq23, a23, a23, lsq23);
            __syncwarp();  // ws reused next q
        }
        __syncwarp();  // csm/idxs reused next batch
    }

    // ---- BN statistics reduction ----
    __syncthreads();
    float s0, s1, s2, s3, q0, q1, q2, q3;
    UNPK2(s0, s1, lsum01); UNPK2(s2, s3, lsum23);
    UNPK2(q0, q1, lsq01);  UNPK2(q2, q3, lsq23);
    int cb = lane * 4;
    atomicAdd(&psum[cb + 0], s0); atomicAdd(&psq[cb + 0], q0);
    atomicAdd(&psum[cb + 1], s1); atomicAdd(&psq[cb + 1], q1);
    atomicAdd(&psum[cb + 2], s2); atomicAdd(&psq[cb + 2], q2);
    atomicAdd(&psum[cb + 3], s3); atomicAdd(&psq[cb + 3], q3);
    __syncthreads();
    if (tid < 128) {
        atomicAdd(&g_sum[tid], psum[tid]);
        atomicAdd(&g_sq[tid],  psq[tid]);
    }
}

// fused stats + normalize + leaky
__global__ __launch_bounds__(256) void kp_norm_kernel(
    float* __restrict__ out,
    const float* __restrict__ gamma,
    const float* __restrict__ beta,
    float invM, int total4)
{
    __shared__ float ssc[128], ssh[128];
    int t = threadIdx.x;
    if (t < 128) {
        float mean = g_sum[t] * invM;
        float var  = fmaxf(g_sq[t] * invM - mean * mean, 0.f);
        float sc   = gamma[t] * rsqrtf(var + 1e-5f);
        ssc[t] = sc;
        ssh[t] = beta[t] - mean * sc;
    }
    __syncthreads();

    int i = blockIdx.x * blockDim.x + t;
    if (i < total4) {
        float4 v = ((float4*)out)[i];
        int cb = (i & 31) * 4;
        v.x = fmaf(v.x, ssc[cb + 0], ssh[cb + 0]);
        v.y = fmaf(v.y, ssc[cb + 1], ssh[cb + 1]);
        v.z = fmaf(v.z, ssc[cb + 2], ssh[cb + 2]);
        v.w = fmaf(v.w, ssc[cb + 3], ssh[cb + 3]);
        v.x = (v.x > 0.f) ? v.x : 0.1f * v.x;
        v.y = (v.y > 0.f) ? v.y : 0.1f * v.y;
        v.z = (v.z > 0.f) ? v.z : 0.1f * v.z;
        v.w = (v.w > 0.f) ? v.w : 0.1f * v.w;
        ((float4*)out)[i] = v;
    }
}

extern "C" void kernel_launch(void* const* d_in, const int* in_sizes, int n_in,
                              void* d_out, int out_size) {
    const float* qp    = (const float*)d_in[0];
    const float* sp    = (const float*)d_in[1];
    const float* sf    = (const float*)d_in[2];
    const int*   nidx  = (const int*)d_in[3];
    const float* kp    = (const float*)d_in[4];
    const float* W1    = (const float*)d_in[5];
    const float* b1    = (const float*)d_in[6];
    const float* W2    = (const float*)d_in[7];
    const float* b2    = (const float*)d_in[8];
    const float* gamma = (const float*)d_in[9];
    const float* beta  = (const float*)d_in[10];
    float* out = (float*)d_out;

    int M = in_sizes[0] / 3;
    int N = in_sizes[2] / C_;
    if (N > NMAX) N = NMAX;

    size_t smem_bytes = (size_t)SMEM_FLOATS * sizeof(float);
    cudaFuncSetAttribute(kp_main_kernel,
                         cudaFuncAttributeMaxDynamicSharedMemorySize, (int)smem_bytes);

    kp_zero_kernel<<<1, 128>>>();
    int cvt4 = N * 32;
    kp_cvt_kernel<<<(cvt4 + 255) / 256, 256>>>(sf, cvt4);
    kp_main_kernel<<<NBLK, THREADS, smem_bytes>>>(qp, sp, sf, nidx, kp, W1, b1, W2, b2, out, M);
    int total4 = M * 32;
    kp_norm_kernel<<<(total4 + 255) / 256, 256>>>(out, gamma, beta, 1.0f / (float)M, total4);
}

// round 5
// speedup vs baseline: 1.7918x; 1.1062x over previous
#include <cuda_runtime.h>
#include <cuda_fp16.h>
#include <math.h>

#define C_ 128
#define H_ 32
#define K_ 15
#define KG_ 120
#define QB 4
#define W1P 132   // pitch W1^T [32][132]
#define W2P 36    // pitch W2^T [128][36]
#define WARPS 8
#define THREADS 256
#define NBLK 296
#define NMAX 30720

// per-warp region (floats): csm 4*128 | hsm 4*32 | cwsm 4*128 | wsT 8*32 | idxs 4*32 | pad
#define OFF_CSM  0
#define OFF_HSM  512
#define OFF_CWSM 640
#define OFF_WST  1152
#define OFF_IDX  1408
#define WARP_SMEM 1544
#define BLOCK_FIXED (32*W1P + 128*W2P + 32 + 128 + 48 + 128 + 128)   // 9296
#define SMEM_FLOATS (BLOCK_FIXED + WARPS*WARP_SMEM)

typedef unsigned long long ull;
#define FMA2(d,a,b,c) asm("fma.rn.f32x2 %0, %1, %2, %3;" : "=l"(d) : "l"(a), "l"(b), "l"(c))
#define ADD2(d,a,b)   asm("add.rn.f32x2 %0, %1, %2;" : "=l"(d) : "l"(a), "l"(b))
#define PACK2(d,x)    asm("mov.b64 %0, {%1, %1};" : "=l"(d) : "f"(x))
#define UNPK2(lo,hi,p) asm("mov.b64 {%0, %1}, %2;" : "=f"(lo), "=f"(hi) : "l"(p))
#define SQRTA(d,x)    asm("sqrt.approx.f32 %0, %1;" : "=f"(d) : "f"(x))
#define F4C(v,c) ((c)==0 ? (v).x : (c)==1 ? (v).y : (c)==2 ? (v).z : (v).w)

__device__ float g_sum[C_];
__device__ float g_sq[C_];
__device__ __align__(16) __half g_sf16[NMAX * C_];

// convert s_feats fp32 -> fp16 cache; block 0 also zeroes the BN accumulators
__global__ void kp_cvt_kernel(const float* __restrict__ sf, int total4) {
    int i = blockIdx.x * blockDim.x + threadIdx.x;
    if (blockIdx.x == 0 && threadIdx.x < C_) {
        g_sum[threadIdx.x] = 0.f;
        g_sq[threadIdx.x]  = 0.f;
    }
    if (i < total4) {
        float4 v = ((const float4*)sf)[i];
        __half2 h0 = __floats2half2_rn(v.x, v.y);
        __half2 h1 = __floats2half2_rn(v.z, v.w);
        uint2 p;
        p.x = *(unsigned int*)&h0;
        p.y = *(unsigned int*)&h1;
        ((uint2*)g_sf16)[i] = p;
    }
}

__global__ __launch_bounds__(THREADS, 2) void kp_main_kernel(
    const float* __restrict__ qp,   // (M,3)
    const float* __restrict__ sp,   // (N,3)
    const float* __restrict__ sf,   // (N,128) fp32
    const int*   __restrict__ nidx, // (M,32)
    const float* __restrict__ kp,   // (15,3)
    const float* __restrict__ W1,   // (128,32)
    const float* __restrict__ b1,   // (32)
    const float* __restrict__ W2,   // (32,120)
    const float* __restrict__ b2,   // (120)
    float* __restrict__ out,        // (M,128) pre-BN
    int M)
{
    extern __shared__ float smem[];
    float* W1t  = smem;                 // [32][132]
    float* W2t  = W1t + 32 * W1P;       // [128][36]
    float* b1s  = W2t + 128 * W2P;      // [32]
    float* b2s  = b1s + 32;             // [128]
    float* kps  = b2s + 128;            // [48]
    float* psum = kps + 48;             // [128]
    float* psq  = psum + 128;           // [128]
    float* wreg = psq + 128;

    const int tid  = threadIdx.x;
    const int wid  = tid >> 5;
    const int lane = tid & 31;

    float* wbase = wreg + wid * WARP_SMEM;
    float* csm   = wbase + OFF_CSM;     // [4][128]
    float* hsm   = wbase + OFF_HSM;     // [4][32]
    float* cwsm  = wbase + OFF_CWSM;    // [4][128]
    float* wsT   = wbase + OFF_WST;     // [8][32]  wsT[g][h]
    int*   idxs  = (int*)(wbase + OFF_IDX); // [4][32]

    for (int e = tid; e < 128 * 32; e += THREADS) {
        int c = e >> 5, i = e & 31;
        W1t[i * W1P + c] = W1[e];
    }
    for (int e = tid; e < 128 * 32; e += THREADS) {
        int i = e >> 7, kg = e & 127;
        W2t[kg * W2P + i] = (kg < KG_) ? W2[i * KG_ + kg] : 0.f;
    }
    if (tid < 32)  b1s[tid] = b1[tid];
    if (tid < 128) { b2s[tid] = (tid < KG_) ? b2[tid] : 0.f; psum[tid] = 0.f; psq[tid] = 0.f; }
    if (tid < 45)  kps[tid] = kp[tid];
    __syncthreads();

    ull lsum01 = 0, lsum23 = 0, lsq01 = 0, lsq23 = 0;

    const int gw = blockIdx.x * WARPS + wid;
    const int nw = gridDim.x * WARPS;
    const int g  = lane >> 2;

    for (int mb = gw * QB; mb < M; mb += nw * QB) {
        // ---- A: neighbor indices + center feats for up to 4 queries ----
        int idxq[QB];
        #pragma unroll
        for (int q = 0; q < QB; q++) {
            int mq = mb + q;
            idxq[q] = (mq < M) ? nidx[mq * H_ + lane] : 0;
            idxs[q * 32 + lane] = idxq[q];
        }
        #pragma unroll
        for (int q = 0; q < QB; q++) {
            int i0 = __shfl_sync(0xffffffffu, idxq[q], 0);
            float4 cf = __ldg(&((const float4*)sf)[i0 * 32 + lane]);
            ((float4*)&csm[q * 128])[lane] = cf;
        }
        __syncwarp();

        // ---- B: batched MLP1 ----
        {
            ull hvp[QB];
            #pragma unroll
            for (int q = 0; q < QB; q++) hvp[q] = 0;
            #pragma unroll 8
            for (int cc = 0; cc < 32; cc++) {
                ulonglong2 w = *(ulonglong2*)&W1t[lane * W1P + cc * 4];
                #pragma unroll
                for (int q = 0; q < QB; q++) {
                    ulonglong2 c = *(ulonglong2*)&csm[q * 128 + cc * 4];
                    FMA2(hvp[q], c.x, w.x, hvp[q]);
                    FMA2(hvp[q], c.y, w.y, hvp[q]);
                }
            }
            float bb = b1s[lane];
            #pragma unroll
            for (int q = 0; q < QB; q++) {
                float lo, hi; UNPK2(lo, hi, hvp[q]);
                float hv = bb + lo + hi;
                hv = (hv > 0.f) ? hv : 0.1f * hv;
                hsm[q * 32 + lane] = hv;
            }
        }
        __syncwarp();

        // ---- C: batched MLP2 ----
        {
            ull accp[4][QB];
            #pragma unroll
            for (int r = 0; r < 4; r++)
                #pragma unroll
                for (int q = 0; q < QB; q++) accp[r][q] = 0;
            #pragma unroll
            for (int ii = 0; ii < 8; ii++) {
                ulonglong2 h2[QB];
                #pragma unroll
                for (int q = 0; q < QB; q++)
                    h2[q] = *(ulonglong2*)&hsm[q * 32 + ii * 4];
                #pragma unroll
                for (int r = 0; r < 4; r++) {
                    ulonglong2 w = *(ulonglong2*)&W2t[(lane + 32 * r) * W2P + ii * 4];
                    #pragma unroll
                    for (int q = 0; q < QB; q++) {
                        FMA2(accp[r][q], h2[q].x, w.x, accp[r][q]);
                        FMA2(accp[r][q], h2[q].y, w.y, accp[r][q]);
                    }
                }
            }
            #pragma unroll
            for (int r = 0; r < 4; r++) {
                int kg = lane + 32 * r;
                float bb = b2s[kg];
                #pragma unroll
                for (int q = 0; q < QB; q++) {
                    float lo, hi; UNPK2(lo, hi, accp[r][q]);
                    cwsm[q * 128 + kg] = bb + lo + hi;
                }
            }
        }
        __syncwarp();

        // ---- D: per query — influence, combine, gather, write ----
        #pragma unroll 1
        for (int q = 0; q < QB; q++) {
            int mq = mb + q;
            if (mq >= M) break;

            // influence (lane = h)
            float qx = qp[mq * 3 + 0], qy = qp[mq * 3 + 1], qz = qp[mq * 3 + 2];
            int myidx = idxq[q];
            float dx = sp[myidx * 3 + 0] - qx;
            float dy = sp[myidx * 3 + 1] - qy;
            float dz = sp[myidx * 3 + 2] - qz;
            float infl[K_];
            #pragma unroll
            for (int k = 0; k < K_; k++) {
                float tx = dx - kps[k * 3 + 0];
                float ty = dy - kps[k * 3 + 1];
                float tz = dz - kps[k * 3 + 2];
                float sq = fmaf(tx, tx, fmaf(ty, ty, tz * tz));
                float d; SQRTA(d, sq);
                infl[k] = fmaxf(1.f - 0.5f * d, 0.f);
            }

            // combine: lane=h computes W[h][g] for g=0..7, writes transposed wsT[g][h]
            {
                ull w01 = 0, w23 = 0, w45 = 0, w67 = 0;
                const float* cwq = &cwsm[q * 128];
                #pragma unroll
                for (int k = 0; k < K_; k++) {
                    ulonglong2 p0 = *(ulonglong2*)&cwq[k * 8];
                    ulonglong2 p1 = *(ulonglong2*)&cwq[k * 8 + 4];
                    ull ik2; PACK2(ik2, infl[k]);
                    FMA2(w01, ik2, p0.x, w01);
                    FMA2(w23, ik2, p0.y, w23);
                    FMA2(w45, ik2, p1.x, w45);
                    FMA2(w67, ik2, p1.y, w67);
                }
                float v0, v1, v2, v3, v4, v5, v6, v7;
                UNPK2(v0, v1, w01); UNPK2(v2, v3, w23);
                UNPK2(v4, v5, w45); UNPK2(v6, v7, w67);
                wsT[0 * 32 + lane] = v0; wsT[1 * 32 + lane] = v1;
                wsT[2 * 32 + lane] = v2; wsT[3 * 32 + lane] = v3;
                wsT[4 * 32 + lane] = v4; wsT[5 * 32 + lane] = v5;
                wsT[6 * 32 + lane] = v6; wsT[7 * 32 + lane] = v7;
            }
            __syncwarp();

            // preload this lane's 32 combine weights into registers
            float4 wq4[8];
            {
                const float4* wrow = (const float4*)&wsT[g * 32];
                #pragma unroll
                for (int i = 0; i < 8; i++) wq4[i] = wrow[i];
            }

            // gather-accumulate over fp16 cache (fully unrolled, weights in regs)
            ull a01 = 0, a23 = 0;
            const int* iq = &idxs[q * 32];
            #pragma unroll
            for (int h = 0; h < H_; h++) {
                float wv = F4C(wq4[h >> 2], (h & 3));
                ull wv2; PACK2(wv2, wv);
                int ih = iq[h];
                uint2 f = *(const uint2*)(g_sf16 + ih * C_ + lane * 4);
                float2 lo = __half22float2(*(__half2*)&f.x);
                float2 hi = __half22float2(*(__half2*)&f.y);
                ull plo = *(ull*)&lo;
                ull phi = *(ull*)&hi;
                FMA2(a01, plo, wv2, a01);
                FMA2(a23, phi, wv2, a23);
            }
            float x0, x1, x2, x3;
            UNPK2(x0, x1, a01);
            UNPK2(x2, x3, a23);
            ((float4*)out)[mq * 32 + lane] = make_float4(x0, x1, x2, x3);
            ADD2(lsum01, lsum01, a01);
            ADD2(lsum23, lsum23, a23);
            FMA2(lsq01, a01, a01, lsq01);
            FMA2(lsq23, a23, a23, lsq23);
            __syncwarp();  // wsT reused next q
        }
        __syncwarp();  // csm/idxs reused next batch
    }

    // ---- BN statistics reduction ----
    __syncthreads();
    float s0, s1, s2, s3, q0, q1, q2, q3;
    UNPK2(s0, s1, lsum01); UNPK2(s2, s3, lsum23);
    UNPK2(q0, q1, lsq01);  UNPK2(q2, q3, lsq23);
    int cb = lane * 4;
    atomicAdd(&psum[cb + 0], s0); atomicAdd(&psq[cb + 0], q0);
    atomicAdd(&psum[cb + 1], s1); atomicAdd(&psq[cb + 1], q1);
    atomicAdd(&psum[cb + 2], s2); atomicAdd(&psq[cb + 2], q2);
    atomicAdd(&psum[cb + 3], s3); atomicAdd(&psq[cb + 3], q3);
    __syncthreads();
    if (tid < 128) {
        atomicAdd(&g_sum[tid], psum[tid]);
        atomicAdd(&g_sq[tid],  psq[tid]);
    }
}

// fused stats + normalize + leaky
__global__ __launch_bounds__(256) void kp_norm_kernel(
    float* __restrict__ out,
    const float* __restrict__ gamma,
    const float* __restrict__ beta,
    float invM, int total4)
{
    __shared__ float ssc[128], ssh[128];
    int t = threadIdx.x;
    if (t < 128) {
        float mean = g_sum[t] * invM;
        float var  = fmaxf(g_sq[t] * invM - mean * mean, 0.f);
        float sc   = gamma[t] * rsqrtf(var + 1e-5f);
        ssc[t] = sc;
        ssh[t] = beta[t] - mean * sc;
    }
    __syncthreads();

    int i = blockIdx.x * blockDim.x + t;
    if (i < total4) {
        float4 v = ((float4*)out)[i];
        int cb = (i & 31) * 4;
        v.x = fmaf(v.x, ssc[cb + 0], ssh[cb + 0]);
        v.y = fmaf(v.y, ssc[cb + 1], ssh[cb + 1]);
        v.z = fmaf(v.z, ssc[cb + 2], ssh[cb + 2]);
        v.w = fmaf(v.w, ssc[cb + 3], ssh[cb + 3]);
        v.x = (v.x > 0.f) ? v.x : 0.1f * v.x;
        v.y = (v.y > 0.f) ? v.y : 0.1f * v.y;
        v.z = (v.z > 0.f) ? v.z : 0.1f * v.z;
        v.w = (v.w > 0.f) ? v.w : 0.1f * v.w;
        ((float4*)out)[i] = v;
    }
}

extern "C" void kernel_launch(void* const* d_in, const int* in_sizes, int n_in,
                              void* d_out, int out_size) {
    const float* qp    = (const float*)d_in[0];
    const float* sp    = (const float*)d_in[1];
    const float* sf    = (const float*)d_in[2];
    const int*   nidx  = (const int*)d_in[3];
    const float* kp    = (const float*)d_in[4];
    const float* W1    = (const float*)d_in[5];
    const float* b1    = (const float*)d_in[6];
    const float* W2    = (const float*)d_in[7];
    const float* b2    = (const float*)d_in[8];
    const float* gamma = (const float*)d_in[9];
    const float* beta  = (const float*)d_in[10];
    float* out = (float*)d_out;

    int M = in_sizes[0] / 3;
    int N = in_sizes[2] / C_;
    if (N > NMAX) N = NMAX;

    size_t smem_bytes = (size_t)SMEM_FLOATS * sizeof(float);
    cudaFuncSetAttribute(kp_main_kernel,
                         cudaFuncAttributeMaxDynamicSharedMemorySize, (int)smem_bytes);

    int cvt4 = N * 32;
    kp_cvt_kernel<<<(cvt4 + 255) / 256, 256>>>(sf, cvt4);
    kp_main_kernel<<<NBLK, THREADS, smem_bytes>>>(qp, sp, sf, nidx, kp, W1, b1, W2, b2, out, M);
    int total4 = M * 32;
    kp_norm_kernel<<<(total4 + 255) / 256, 256>>>(out, gamma, beta, 1.0f / (float)M, total4);
}

// round 6
// speedup vs baseline: 1.8263x; 1.0193x over previous
#include <cuda_runtime.h>
#include <cuda_fp16.h>
#include <math.h>

#define C_ 128
#define H_ 32
#define K_ 15
#define KG_ 120
#define QB 4
#define W1P 132   // pitch W1^T [32][132]
#define W2P 36    // pitch W2^T [128][36]
#define WARPS 8
#define THREADS 256
#define NBLK 296
#define NMAX 30720

// per-warp region (floats): csm 512 | hsm 128 | cwsm 512 | ws 4*256 | idxs 128 | pad
#define OFF_CSM  0
#define OFF_HSM  512
#define OFF_CWSM 640
#define OFF_WS   1152
#define OFF_IDX  2176
#define WARP_SMEM 2312
#define BLOCK_FIXED (32*W1P + 128*W2P + 32 + 128 + 48 + 128 + 128)   // 9296
#define SMEM_FLOATS (BLOCK_FIXED + WARPS*WARP_SMEM)                   // 27792 fl = 111.2KB

typedef unsigned long long ull;
#define FMA2(d,a,b,c) asm("fma.rn.f32x2 %0, %1, %2, %3;" : "=l"(d) : "l"(a), "l"(b), "l"(c))
#define ADD2(d,a,b)   asm("add.rn.f32x2 %0, %1, %2;" : "=l"(d) : "l"(a), "l"(b))
#define PACK2(d,x)    asm("mov.b64 %0, {%1, %1};" : "=l"(d) : "f"(x))
#define UNPK2(lo,hi,p) asm("mov.b64 {%0, %1}, %2;" : "=f"(lo), "=f"(hi) : "l"(p))
#define SQRTA(d,x)    asm("sqrt.approx.f32 %0, %1;" : "=f"(d) : "f"(x))

__device__ float g_sum[C_];
__device__ float g_sq[C_];
__device__ __align__(16) __half g_sf16[NMAX * C_];

// convert s_feats fp32 -> fp16 cache; block 0 also zeroes the BN accumulators
__global__ void kp_cvt_kernel(const float* __restrict__ sf, int total4) {
    int i = blockIdx.x * blockDim.x + threadIdx.x;
    if (blockIdx.x == 0 && threadIdx.x < C_) {
        g_sum[threadIdx.x] = 0.f;
        g_sq[threadIdx.x]  = 0.f;
    }
    if (i < total4) {
        float4 v = ((const float4*)sf)[i];
        __half2 h0 = __floats2half2_rn(v.x, v.y);
        __half2 h1 = __floats2half2_rn(v.z, v.w);
        uint2 p;
        p.x = *(unsigned int*)&h0;
        p.y = *(unsigned int*)&h1;
        ((uint2*)g_sf16)[i] = p;
    }
}

__global__ __launch_bounds__(THREADS, 2) void kp_main_kernel(
    const float* __restrict__ qp,   // (M,3)
    const float* __restrict__ sp,   // (N,3)
    const float* __restrict__ sf,   // (N,128) fp32
    const int*   __restrict__ nidx, // (M,32)
    const float* __restrict__ kp,   // (15,3)
    const float* __restrict__ W1,   // (128,32)
    const float* __restrict__ b1,   // (32)
    const float* __restrict__ W2,   // (32,120)
    const float* __restrict__ b2,   // (120)
    float* __restrict__ out,        // (M,128) pre-BN
    int M)
{
    extern __shared__ float smem[];
    float* W1t  = smem;                 // [32][132]
    float* W2t  = W1t + 32 * W1P;       // [128][36]
    float* b1s  = W2t + 128 * W2P;      // [32]
    float* b2s  = b1s + 32;             // [128]
    float* kps  = b2s + 128;            // [48]
    float* psum = kps + 48;             // [128]
    float* psq  = psum + 128;           // [128]
    float* wreg = psq + 128;

    const int tid  = threadIdx.x;
    const int wid  = tid >> 5;
    const int lane = tid & 31;

    float* wbase = wreg + wid * WARP_SMEM;
    float* csm   = wbase + OFF_CSM;     // [4][128]
    float* hsm   = wbase + OFF_HSM;     // [4][32]
    float* cwsm  = wbase + OFF_CWSM;    // [4][128]
    float* ws    = wbase + OFF_WS;      // [4][32][8]  ws[q][h][g]
    int*   idxs  = (int*)(wbase + OFF_IDX); // [4][32]

    for (int e = tid; e < 128 * 32; e += THREADS) {
        int c = e >> 5, i = e & 31;
        W1t[i * W1P + c] = W1[e];
    }
    for (int e = tid; e < 128 * 32; e += THREADS) {
        int i = e >> 7, kg = e & 127;
        W2t[kg * W2P + i] = (kg < KG_) ? W2[i * KG_ + kg] : 0.f;
    }
    if (tid < 32)  b1s[tid] = b1[tid];
    if (tid < 128) { b2s[tid] = (tid < KG_) ? b2[tid] : 0.f; psum[tid] = 0.f; psq[tid] = 0.f; }
    if (tid < 45)  kps[tid] = kp[tid];
    __syncthreads();

    ull lsum01 = 0, lsum23 = 0, lsq01 = 0, lsq23 = 0;

    const int gw = blockIdx.x * WARPS + wid;
    const int nw = gridDim.x * WARPS;
    const int g  = lane >> 2;

    for (int mb = gw * QB; mb < M; mb += nw * QB) {
        // ---- A: neighbor indices + center feats for up to 4 queries ----
        int idxq[QB];
        #pragma unroll
        for (int q = 0; q < QB; q++) {
            int mq = mb + q;
            idxq[q] = (mq < M) ? nidx[mq * H_ + lane] : 0;
            idxs[q * 32 + lane] = idxq[q];
        }
        #pragma unroll
        for (int q = 0; q < QB; q++) {
            int i0 = __shfl_sync(0xffffffffu, idxq[q], 0);
            float4 cf = __ldg(&((const float4*)sf)[i0 * 32 + lane]);
            ((float4*)&csm[q * 128])[lane] = cf;
        }
        __syncwarp();

        // ---- B: batched MLP1 ----
        {
            ull hvp[QB];
            #pragma unroll
            for (int q = 0; q < QB; q++) hvp[q] = 0;
            #pragma unroll 8
            for (int cc = 0; cc < 32; cc++) {
                ulonglong2 w = *(ulonglong2*)&W1t[lane * W1P + cc * 4];
                #pragma unroll
                for (int q = 0; q < QB; q++) {
                    ulonglong2 c = *(ulonglong2*)&csm[q * 128 + cc * 4];
                    FMA2(hvp[q], c.x, w.x, hvp[q]);
                    FMA2(hvp[q], c.y, w.y, hvp[q]);
                }
            }
            float bb = b1s[lane];
            #pragma unroll
            for (int q = 0; q < QB; q++) {
                float lo, hi; UNPK2(lo, hi, hvp[q]);
                float hv = bb + lo + hi;
                hv = (hv > 0.f) ? hv : 0.1f * hv;
                hsm[q * 32 + lane] = hv;
            }
        }
        __syncwarp();

        // ---- C: batched MLP2 ----
        {
            ull accp[4][QB];
            #pragma unroll
            for (int r = 0; r < 4; r++)
                #pragma unroll
                for (int q = 0; q < QB; q++) accp[r][q] = 0;
            #pragma unroll
            for (int ii = 0; ii < 8; ii++) {
                ulonglong2 h2[QB];
                #pragma unroll
                for (int q = 0; q < QB; q++)
                    h2[q] = *(ulonglong2*)&hsm[q * 32 + ii * 4];
                #pragma unroll
                for (int r = 0; r < 4; r++) {
                    ulonglong2 w = *(ulonglong2*)&W2t[(lane + 32 * r) * W2P + ii * 4];
                    #pragma unroll
                    for (int q = 0; q < QB; q++) {
                        FMA2(accp[r][q], h2[q].x, w.x, accp[r][q]);
                        FMA2(accp[r][q], h2[q].y, w.y, accp[r][q]);
                    }
                }
            }
            #pragma unroll
            for (int r = 0; r < 4; r++) {
                int kg = lane + 32 * r;
                float bb = b2s[kg];
                #pragma unroll
                for (int q = 0; q < QB; q++) {
                    float lo, hi; UNPK2(lo, hi, accp[r][q]);
                    cwsm[q * 128 + kg] = bb + lo + hi;
                }
            }
        }
        __syncwarp();

        // ---- D: influence + combine for ALL 4 queries (lane = h) ----
        #pragma unroll 1
        for (int q = 0; q < QB; q++) {
            int mq = mb + q;
            int mc = (mq < M) ? mq : (M - 1);   // clamp; pad results discarded

            float qx = qp[mc * 3 + 0], qy = qp[mc * 3 + 1], qz = qp[mc * 3 + 2];
            int myidx = idxq[q];
            float dx = sp[myidx * 3 + 0] - qx;
            float dy = sp[myidx * 3 + 1] - qy;
            float dz = sp[myidx * 3 + 2] - qz;
            float infl[K_];
            #pragma unroll
            for (int k = 0; k < K_; k++) {
                float tx = dx - kps[k * 3 + 0];
                float ty = dy - kps[k * 3 + 1];
                float tz = dz - kps[k * 3 + 2];
                float sq = fmaf(tx, tx, fmaf(ty, ty, tz * tz));
                float d; SQRTA(d, sq);
                infl[k] = fmaxf(1.f - 0.5f * d, 0.f);
            }

            ull w01 = 0, w23 = 0, w45 = 0, w67 = 0;
            const float* cwq = &cwsm[q * 128];
            #pragma unroll
            for (int k = 0; k < K_; k++) {
                ulonglong2 p0 = *(ulonglong2*)&cwq[k * 8];
                ulonglong2 p1 = *(ulonglong2*)&cwq[k * 8 + 4];
                ull ik2; PACK2(ik2, infl[k]);
                FMA2(w01, ik2, p0.x, w01);
                FMA2(w23, ik2, p0.y, w23);
                FMA2(w45, ik2, p1.x, w45);
                FMA2(w67, ik2, p1.y, w67);
            }
            ulonglong2* wrow = (ulonglong2*)&ws[q * 256 + lane * 8];
            wrow[0] = make_ulonglong2(w01, w23);
            wrow[1] = make_ulonglong2(w45, w67);
        }
        __syncwarp();

        // ---- E: interleaved gather-accumulate for 4 queries ----
        {
            ull a01[QB], a23[QB];
            #pragma unroll
            for (int q = 0; q < QB; q++) { a01[q] = 0; a23[q] = 0; }

            #pragma unroll 8
            for (int h = 0; h < H_; h++) {
                #pragma unroll
                for (int q = 0; q < QB; q++) {
                    float wv = ws[q * 256 + h * 8 + g];
                    ull wv2; PACK2(wv2, wv);
                    int ih = idxs[q * 32 + h];
                    uint2 f = *(const uint2*)(g_sf16 + ih * C_ + lane * 4);
                    float2 lo = __half22float2(*(__half2*)&f.x);
                    float2 hi = __half22float2(*(__half2*)&f.y);
                    ull plo = *(ull*)&lo;
                    ull phi = *(ull*)&hi;
                    FMA2(a01[q], plo, wv2, a01[q]);
                    FMA2(a23[q], phi, wv2, a23[q]);
                }
            }

            #pragma unroll
            for (int q = 0; q < QB; q++) {
                int mq = mb + q;
                if (mq < M) {
                    float x0, x1, x2, x3;
                    UNPK2(x0, x1, a01[q]);
                    UNPK2(x2, x3, a23[q]);
                    ((float4*)out)[mq * 32 + lane] = make_float4(x0, x1, x2, x3);
                    ADD2(lsum01, lsum01, a01[q]);
                    ADD2(lsum23, lsum23, a23[q]);
                    FMA2(lsq01, a01[q], a01[q], lsq01);
                    FMA2(lsq23, a23[q], a23[q], lsq23);
                }
            }
        }
        __syncwarp();  // smem regions reused next batch
    }

    // ---- BN statistics reduction ----
    __syncthreads();
    float s0, s1, s2, s3, q0, q1, q2, q3;
    UNPK2(s0, s1, lsum01); UNPK2(s2, s3, lsum23);
    UNPK2(q0, q1, lsq01);  UNPK2(q2, q3, lsq23);
    int cb = lane * 4;
    atomicAdd(&psum[cb + 0], s0); atomicAdd(&psq[cb + 0], q0);
    atomicAdd(&psum[cb + 1], s1); atomicAdd(&psq[cb + 1], q1);
    atomicAdd(&psum[cb + 2], s2); atomicAdd(&psq[cb + 2], q2);
    atomicAdd(&psum[cb + 3], s3); atomicAdd(&psq[cb + 3], q3);
    __syncthreads();
    if (tid < 128) {
        atomicAdd(&g_sum[tid], psum[tid]);
        atomicAdd(&g_sq[tid],  psq[tid]);
    }
}

// fused stats + normalize + leaky
__global__ __launch_bounds__(256) void kp_norm_kernel(
    float* __restrict__ out,
    const float* __restrict__ gamma,
    const float* __restrict__ beta,
    float invM, int total4)
{
    __shared__ float ssc[128], ssh[128];
    int t = threadIdx.x;
    if (t < 128) {
        float mean = g_sum[t] * invM;
        float var  = fmaxf(g_sq[t] * invM - mean * mean, 0.f);
        float sc   = gamma[t] * rsqrtf(var + 1e-5f);
        ssc[t] = sc;
        ssh[t] = beta[t] - mean * sc;
    }
    __syncthreads();

    int i = blockIdx.x * blockDim.x + t;
    if (i < total4) {
        float4 v = ((float4*)out)[i];
        int cb = (i & 31) * 4;
        v.x = fmaf(v.x, ssc[cb + 0], ssh[cb + 0]);
        v.y = fmaf(v.y, ssc[cb + 1], ssh[cb + 1]);
        v.z = fmaf(v.z, ssc[cb + 2], ssh[cb + 2]);
        v.w = fmaf(v.w, ssc[cb + 3], ssh[cb + 3]);
        v.x = (v.x > 0.f) ? v.x : 0.1f * v.x;
        v.y = (v.y > 0.f) ? v.y : 0.1f * v.y;
        v.z = (v.z > 0.f) ? v.z : 0.1f * v.z;
        v.w = (v.w > 0.f) ? v.w : 0.1f * v.w;
        ((float4*)out)[i] = v;
    }
}

extern "C" void kernel_launch(void* const* d_in, const int* in_sizes, int n_in,
                              void* d_out, int out_size) {
    const float* qp    = (const float*)d_in[0];
    const float* sp    = (const float*)d_in[1];
    const float* sf    = (const float*)d_in[2];
    const int*   nidx  = (const int*)d_in[3];
    const float* kp    = (const float*)d_in[4];
    const float* W1    = (const float*)d_in[5];
    const float* b1    = (const float*)d_in[6];
    const float* W2    = (const float*)d_in[7];
    const float* b2    = (const float*)d_in[8];
    const float* gamma = (const float*)d_in[9];
    const float* beta  = (const float*)d_in[10];
    float* out = (float*)d_out;

    int M = in_sizes[0] / 3;
    int N = in_sizes[2] / C_;
    if (N > NMAX) N = NMAX;

    size_t smem_bytes = (size_t)SMEM_FLOATS * sizeof(float);
    cudaFuncSetAttribute(kp_main_kernel,
                         cudaFuncAttributeMaxDynamicSharedMemorySize, (int)smem_bytes);

    int cvt4 = N * 32;
    kp_cvt_kernel<<<(cvt4 + 255) / 256, 256>>>(sf, cvt4);
    kp_main_kernel<<<NBLK, THREADS, smem_bytes>>>(qp, sp, sf, nidx, kp, W1, b1, W2, b2, out, M);
    int total4 = M * 32;
    kp_norm_kernel<<<(total4 + 255) / 256, 256>>>(out, gamma, beta, 1.0f / (float)M, total4);
}